// round 3
// baseline (speedup 1.0000x reference)
#include <cuda_runtime.h>

#define NN 100000
#define NE 3200000
#define NG 1024
#define D  128
#define BN_EPS 1e-5f

// ---------------- scratch (static device globals; no runtime alloc) ----------
__device__ float g_agg[(size_t)NN * D];   // hin = h + sum_neighbors
__device__ float g_h1 [(size_t)NN * D];   // pre-BN hidden
__device__ float g_hA [(size_t)NN * D];   // layer output ping
__device__ float g_hB [(size_t)NN * D];   // layer output pong
__device__ int   g_rowptr[NN + 1];
__device__ int   g_cnt[NN];               // histogram, then fill cursor
__device__ int   g_csrc[NE];              // CSR: src node ids grouped by dst
__device__ float g_stats[2 * D];          // col sum, col sumsq
__device__ float g_scale[D];
__device__ float g_shift[D];
__device__ float g_pooled[(size_t)NG * 4 * D];
__device__ int   g_gstart[NG + 1];
__device__ float g_c1[NG * D];
__device__ float g_c2[NG * (D / 2)];

// ---------------- CSR build ---------------------------------------------------
__global__ void k_zero_cnt() {
    int i = blockIdx.x * blockDim.x + threadIdx.x;
    if (i < NN) g_cnt[i] = 0;
}

__global__ void k_hist(const int* __restrict__ dst) {
    for (int e = blockIdx.x * blockDim.x + threadIdx.x; e < NE; e += gridDim.x * blockDim.x)
        atomicAdd(&g_cnt[dst[e]], 1);
}

__global__ void k_scan() {   // one block, 1024 threads
    __shared__ int totals[1024];
    int t = threadIdx.x;
    const int CH = (NN + 1023) / 1024;   // 98
    int start = t * CH;
    int end   = start + CH; if (end > NN) end = NN;
    int s = 0;
    for (int i = start; i < end; i++) s += g_cnt[i];
    totals[t] = s;
    __syncthreads();
    if (t == 0) {
        int run = 0;
        for (int i = 0; i < 1024; i++) { int v = totals[i]; totals[i] = run; run += v; }
        g_rowptr[NN] = run;   // == NE
    }
    __syncthreads();
    int run = totals[t];
    for (int i = start; i < end; i++) { g_rowptr[i] = run; run += g_cnt[i]; }
}

__global__ void k_scatter(const int* __restrict__ src, const int* __restrict__ dst) {
    for (int e = blockIdx.x * blockDim.x + threadIdx.x; e < NE; e += gridDim.x * blockDim.x) {
        int d = dst[e];
        int pos = g_rowptr[d] + atomicAdd(&g_cnt[d], 1);
        g_csrc[pos] = src[e];
    }
}

// batch is sorted: find graph boundaries by binary search
__global__ void k_gstart(const int* __restrict__ batch) {
    int g = blockIdx.x * blockDim.x + threadIdx.x;
    if (g > NG) return;
    if (g == NG) { g_gstart[NG] = NN; return; }
    int lo = 0, hi = NN;
    while (lo < hi) { int mid = (lo + hi) >> 1; if (batch[mid] < g) lo = mid + 1; else hi = mid; }
    g_gstart[g] = lo;
}

// ---------------- aggregation: hin[i] = h[i] + sum_{e in CSR(i)} h[src(e)] ----
__global__ void k_agg(const float* __restrict__ h) {
    int i = blockIdx.x;
    int t = threadIdx.x;
    int e0 = g_rowptr[i], e1 = g_rowptr[i + 1];
    float acc = h[(size_t)i * D + t];
    int e = e0;
    // unroll-4: batch the index loads so the row gathers overlap (MLP>=4)
    for (; e + 4 <= e1; e += 4) {
        int s0 = g_csrc[e], s1 = g_csrc[e + 1], s2 = g_csrc[e + 2], s3 = g_csrc[e + 3];
        float v0 = h[(size_t)s0 * D + t];
        float v1 = h[(size_t)s1 * D + t];
        float v2 = h[(size_t)s2 * D + t];
        float v3 = h[(size_t)s3 * D + t];
        acc += (v0 + v1) + (v2 + v3);
    }
    for (; e < e1; e++) acc += h[(size_t)g_csrc[e] * D + t];
    g_agg[(size_t)i * D + t] = acc;
}

// ---------------- GEMM: C[M,128] = op(A)[M,128] @ W[128,128] + b --------------
// MODE 0: plain A, no output relu (GEMM1, pre-BN)
// MODE 1: A' = relu(A*scale + shift) per column (fused BN+ReLU), output relu
template <int MODE>
__global__ void __launch_bounds__(256) k_gemm(const float* __restrict__ A,
                                              const float* __restrict__ W,
                                              const float* __restrict__ bias,
                                              float* __restrict__ C) {
    __shared__ float As[64][36];     // 64 rows x 32 K-cols (padded)
    __shared__ float Ws[32][128];    // 32 K-rows x 128 cols
    int tid = threadIdx.x;
    int tc = tid & 31;               // col group (4 cols)
    int tr = tid >> 5;               // row group (8 rows); constant within warp
    int m0 = blockIdx.x * 64;

    float acc[8][4];
#pragma unroll
    for (int r = 0; r < 8; r++)
#pragma unroll
        for (int c = 0; c < 4; c++) acc[r][c] = 0.f;

    for (int k0 = 0; k0 < D; k0 += 32) {
#pragma unroll
        for (int j = 0; j < 2; j++) {        // A tile: 512 float4, 2/thread
            int f = tid * 2 + j;
            int r = f >> 3, kq = f & 7;
            int row = m0 + r;
            float4 v = make_float4(0.f, 0.f, 0.f, 0.f);
            if (row < NN) v = *(const float4*)(A + (size_t)row * D + k0 + kq * 4);
            if (MODE == 1) {
                float4 sc = *(const float4*)(g_scale + k0 + kq * 4);
                float4 sh = *(const float4*)(g_shift + k0 + kq * 4);
                v.x = fmaxf(fmaf(v.x, sc.x, sh.x), 0.f);
                v.y = fmaxf(fmaf(v.y, sc.y, sh.y), 0.f);
                v.z = fmaxf(fmaf(v.z, sc.z, sh.z), 0.f);
                v.w = fmaxf(fmaf(v.w, sc.w, sh.w), 0.f);
            }
            *(float4*)&As[r][kq * 4] = v;
        }
#pragma unroll
        for (int j = 0; j < 4; j++) {        // W tile: 1024 float4, 4/thread
            int f = j * 256 + tid;
            int k = f >> 5, q = f & 31;
            *(float4*)&Ws[k][q * 4] = *(const float4*)(W + (size_t)(k0 + k) * D + q * 4);
        }
        __syncthreads();
#pragma unroll
        for (int k = 0; k < 32; k++) {
            float4 wv = *(const float4*)&Ws[k][tc * 4];
#pragma unroll
            for (int r = 0; r < 8; r++) {
                float a = As[tr * 8 + r][k];    // broadcast within warp
                acc[r][0] = fmaf(a, wv.x, acc[r][0]);
                acc[r][1] = fmaf(a, wv.y, acc[r][1]);
                acc[r][2] = fmaf(a, wv.z, acc[r][2]);
                acc[r][3] = fmaf(a, wv.w, acc[r][3]);
            }
        }
        __syncthreads();
    }

    float4 bv = *(const float4*)(bias + tc * 4);
#pragma unroll
    for (int r = 0; r < 8; r++) {
        int row = m0 + tr * 8 + r;
        if (row < NN) {
            float4 o;
            o.x = acc[r][0] + bv.x;
            o.y = acc[r][1] + bv.y;
            o.z = acc[r][2] + bv.z;
            o.w = acc[r][3] + bv.w;
            if (MODE == 1) {
                o.x = fmaxf(o.x, 0.f); o.y = fmaxf(o.y, 0.f);
                o.z = fmaxf(o.z, 0.f); o.w = fmaxf(o.w, 0.f);
            }
            *(float4*)(C + (size_t)row * D + tc * 4) = o;
        }
    }
}

// ---------------- BN statistics over g_h1 ------------------------------------
__global__ void k_zero_stats() { int i = threadIdx.x; if (i < 2 * D) g_stats[i] = 0.f; }

__global__ void k_stats() {      // grid 512 x 128
    int t = threadIdx.x;
    float s = 0.f, s2 = 0.f;
    for (int r = blockIdx.x; r < NN; r += gridDim.x) {
        float v = g_h1[(size_t)r * D + t];
        s += v;
        s2 = fmaf(v, v, s2);
    }
    atomicAdd(&g_stats[t], s);
    atomicAdd(&g_stats[D + t], s2);
}

__global__ void k_finalize(const float* __restrict__ gamma, const float* __restrict__ beta) {
    int c = threadIdx.x;
    float mean = g_stats[c] * (1.f / NN);
    float var  = g_stats[D + c] * (1.f / NN) - mean * mean;  // biased var
    float sc   = gamma[c] * rsqrtf(var + BN_EPS);
    g_scale[c] = sc;
    g_shift[c] = fmaf(-mean, sc, beta[c]);
}

// ---------------- per-graph pooling (sorted batch -> contiguous ranges) ------
__global__ void k_pool(const float* __restrict__ h, int layer) {
    int g = blockIdx.x, t = threadIdx.x;
    int i0 = g_gstart[g], i1 = g_gstart[g + 1];
    float s = 0.f;
    for (int i = i0; i < i1; i++) s += h[(size_t)i * D + t];
    g_pooled[(size_t)g * (4 * D) + layer * D + t] = s;
}

// ---------------- classifier --------------------------------------------------
__global__ void k_cls1(const float* __restrict__ cw1, const float* __restrict__ cb1) {
    int g = blockIdx.x, c = threadIdx.x;     // 128 threads
    const float* p = g_pooled + (size_t)g * (4 * D);
    float s = cb1[c];
#pragma unroll 8
    for (int k = 0; k < 4 * D; k++) s = fmaf(p[k], cw1[(size_t)k * D + c], s);
    g_c1[g * D + c] = fmaxf(s, 0.f);
}

__global__ void k_cls2(const float* __restrict__ cw2, const float* __restrict__ cb2) {
    int g = blockIdx.x, c = threadIdx.x;     // 64 threads
    const float* p = g_c1 + g * D;
    float s = cb2[c];
#pragma unroll 8
    for (int k = 0; k < D; k++) s = fmaf(p[k], cw2[k * (D / 2) + c], s);
    g_c2[g * (D / 2) + c] = fmaxf(s, 0.f);
}

__global__ void k_cls3(const float* __restrict__ cw3, const float* __restrict__ cb3,
                       float* __restrict__ out) {
    int id = blockIdx.x * blockDim.x + threadIdx.x;
    if (id >= NG * 2) return;
    int g = id >> 1, c = id & 1;
    const float* p = g_c2 + g * (D / 2);
    float s = cb3[c];
#pragma unroll
    for (int k = 0; k < D / 2; k++) s = fmaf(p[k], cw3[k * 2 + c], s);
    out[id] = s;
}

// ---------------- launcher ----------------------------------------------------
extern "C" void kernel_launch(void* const* d_in, const int* in_sizes, int n_in,
                              void* d_out, int out_size) {
    const float* x    = (const float*)d_in[0];
    const int*   ei   = (const int*)  d_in[1];
    const int*   bat  = (const int*)  d_in[2];
    const float* w1   = (const float*)d_in[3];
    const float* b1   = (const float*)d_in[4];
    const float* g1   = (const float*)d_in[5];
    const float* be1  = (const float*)d_in[6];
    const float* w2   = (const float*)d_in[7];
    const float* b2   = (const float*)d_in[8];
    const float* lw1  = (const float*)d_in[9];
    const float* lb1  = (const float*)d_in[10];
    const float* lg1  = (const float*)d_in[11];
    const float* lbe1 = (const float*)d_in[12];
    const float* lw2  = (const float*)d_in[13];
    const float* lb2  = (const float*)d_in[14];
    const float* cw1  = (const float*)d_in[15];
    const float* cb1  = (const float*)d_in[16];
    const float* cw2  = (const float*)d_in[17];
    const float* cb2  = (const float*)d_in[18];
    const float* cw3  = (const float*)d_in[19];
    const float* cb3  = (const float*)d_in[20];
    const int* src = ei;
    const int* dst = ei + NE;

    float *pAgg, *pH1, *pHA, *pHB;
    cudaGetSymbolAddress((void**)&pAgg, g_agg);
    cudaGetSymbolAddress((void**)&pH1,  g_h1);
    cudaGetSymbolAddress((void**)&pHA,  g_hA);
    cudaGetSymbolAddress((void**)&pHB,  g_hB);

    // CSR by dst (rebuilt every call; deterministic)
    k_zero_cnt<<<(NN + 255) / 256, 256>>>();
    k_hist<<<2048, 256>>>(dst);
    k_scan<<<1, 1024>>>();
    k_zero_cnt<<<(NN + 255) / 256, 256>>>();
    k_scatter<<<2048, 256>>>(src, dst);
    k_gstart<<<5, 256>>>(bat);

    const int GB = (NN + 63) / 64;   // 1563 tiles
    const float* H = x;
    for (int l = 0; l < 4; l++) {
        const float *W1, *B1, *G, *BE, *W2, *B2;
        if (l == 0) { W1 = w1; B1 = b1; G = g1; BE = be1; W2 = w2; B2 = b2; }
        else {
            W1 = lw1 + (size_t)(l - 1) * D * D;  B1 = lb1 + (l - 1) * D;
            G  = lg1 + (l - 1) * D;              BE = lbe1 + (l - 1) * D;
            W2 = lw2 + (size_t)(l - 1) * D * D;  B2 = lb2 + (l - 1) * D;
        }
        k_agg<<<NN, 128>>>(H);
        k_gemm<0><<<GB, 256>>>(pAgg, W1, B1, pH1);
        k_zero_stats<<<1, 256>>>();
        k_stats<<<512, 128>>>();
        k_finalize<<<1, 128>>>(G, BE);
        float* Hout = (l & 1) ? pHB : pHA;
        k_gemm<1><<<GB, 256>>>(pH1, W2, B2, Hout);
        k_pool<<<NG, 128>>>(Hout, l);
        H = Hout;
    }

    k_cls1<<<NG, 128>>>(cw1, cb1);
    k_cls2<<<NG, 64>>>(cw2, cb2);
    k_cls3<<<8, 256>>>(cw3, cb3, (float*)d_out);
}